// round 16
// baseline (speedup 1.0000x reference)
#include <cuda_runtime.h>
#include <math.h>
#include <stdint.h>
#include <stddef.h>

// Problem constants
#define Tq 512
#define Sk 2048
#define NB 8
#define E  1024
#define H  8
#define HD 128
#define EPSF 1e-5f
#define SCALE 0.08838834764831845f   // HD^-0.5

// GEMM tiling: 256x128 block tile, 8x8 micro-tile, 512 threads (4 warps/SMSP)
#define BM 256
#define BN 128
#define BK 16
#define NT 512
#define ASTR 260
#define BSTR 132
#define SMEMB ((2*BK*ASTR + 2*BK*BSTR) * 4)   // 50176 bytes

// Unified projection grid: KV tiles then Q tiles
#define KV_TILES 1024     // (2E/BN=16) x (Sk*NB/BM=64)
#define Q_TILES  128      // (E/BN=8)  x (Tq*NB/BM=16)

// Scratch (device globals: allocation-free per harness rules)
__device__ __align__(128) float g_q   [(size_t)NB*H*Tq*HD];
__device__ __align__(128) float g_k   [(size_t)NB*H*Sk*HD];
__device__ __align__(128) float g_v   [(size_t)NB*H*Sk*HD];
__device__ __align__(128) float g_w   [(size_t)NB*H*Tq*Sk];
__device__ __align__(128) float g_attn[(size_t)Tq*NB*E];
__device__ __align__(128) float g_pre [(size_t)Tq*NB*E];

typedef unsigned long long u64;

__device__ __forceinline__ u64 splat2(float x) {
    u64 r;
    asm("mov.b64 %0, {%1, %1};" : "=l"(r) : "f"(x));
    return r;
}
__device__ __forceinline__ void ffma2(u64 &d, u64 a, u64 b) {
    asm("fma.rn.f32x2 %0, %1, %2, %0;" : "+l"(d) : "l"(a), "l"(b));
}

// ---------------------------------------------------------------------------
// Loaders / stores (512 threads)
// A tile: 256 rows x 16 k = 1024 float4 -> 2 per thread
// B tile: 128 rows x 16 k (or 16 x 128)  = 512 float4 -> 1 per thread
// ---------------------------------------------------------------------------
__device__ __forceinline__ void loadA(float4 pa[2], const float* __restrict__ A,
                                      int lda, int r0, int k0) {
    const int tid = threadIdx.x;
    #pragma unroll
    for (int l = 0; l < 2; l++) {
        int idx = tid + l*NT;
        int row = idx >> 2;
        int q   = (idx & 3) * 4;
        pa[l] = *reinterpret_cast<const float4*>(&A[(size_t)(r0+row)*lda + k0 + q]);
    }
}
__device__ __forceinline__ void storeA(float* As, const float4 pa[2]) {
    const int tid = threadIdx.x;
    #pragma unroll
    for (int l = 0; l < 2; l++) {
        int idx = tid + l*NT;
        int row = idx >> 2;
        int q   = (idx & 3) * 4;
        As[(q+0)*ASTR + row] = pa[l].x;
        As[(q+1)*ASTR + row] = pa[l].y;
        As[(q+2)*ASTR + row] = pa[l].z;
        As[(q+3)*ASTR + row] = pa[l].w;
    }
}
__device__ __forceinline__ void loadBt(float4 &pb, const float* __restrict__ Bm,
                                       int ldb, int c0, int k0) {
    const int tid = threadIdx.x;
    int row = tid >> 2;
    int q   = (tid & 3) * 4;
    pb = *reinterpret_cast<const float4*>(&Bm[(size_t)(c0+row)*ldb + k0 + q]);
}
__device__ __forceinline__ void storeBt(float* Bs, const float4 &pb) {
    const int tid = threadIdx.x;
    int row = tid >> 2;
    int q   = (tid & 3) * 4;
    Bs[(q+0)*BSTR + row] = pb.x;
    Bs[(q+1)*BSTR + row] = pb.y;
    Bs[(q+2)*BSTR + row] = pb.z;
    Bs[(q+3)*BSTR + row] = pb.w;
}
__device__ __forceinline__ void loadBn(float4 &pb, const float* __restrict__ Bm,
                                       int ldb, int c0, int k0) {
    const int tid = threadIdx.x;
    int kk = tid >> 5;
    int c4 = (tid & 31) * 4;
    pb = *reinterpret_cast<const float4*>(&Bm[(size_t)(k0+kk)*ldb + c0 + c4]);
}
__device__ __forceinline__ void storeBn(float* Bs, const float4 &pb) {
    const int tid = threadIdx.x;
    int kk = tid >> 5;
    int c4 = (tid & 31) * 4;
    *reinterpret_cast<float4*>(&Bs[kk*BSTR + c4]) = pb;
}

// ---------------------------------------------------------------------------
// FFMA2 inner product: 8x8 micro-tile (4 row-pairs x 8 cols)
// ty = tid>>4 (0..31): rows ty*8..ty*8+7; tx = tid&15: cols tx*8..tx*8+7
// ---------------------------------------------------------------------------
__device__ __forceinline__ void compute_tile(u64 acc[4][8],
                                             const float* As, const float* Bs,
                                             int ty, int tx) {
    #pragma unroll
    for (int kk = 0; kk < BK; kk++) {
        const float* ap = As + kk*ASTR + ty*8;
        ulonglong2 a0 = *reinterpret_cast<const ulonglong2*>(ap);
        ulonglong2 a1 = *reinterpret_cast<const ulonglong2*>(ap + 4);
        u64 av[4] = {a0.x, a0.y, a1.x, a1.y};
        const float* bp = Bs + kk*BSTR + tx*8;
        float4 b0 = *reinterpret_cast<const float4*>(bp);
        float4 b1 = *reinterpret_cast<const float4*>(bp + 4);
        u64 bv[8];
        bv[0]=splat2(b0.x); bv[1]=splat2(b0.y); bv[2]=splat2(b0.z); bv[3]=splat2(b0.w);
        bv[4]=splat2(b1.x); bv[5]=splat2(b1.y); bv[6]=splat2(b1.z); bv[7]=splat2(b1.w);
        #pragma unroll
        for (int ip = 0; ip < 4; ip++) {
            #pragma unroll
            for (int j = 0; j < 8; j++)
                ffma2(acc[ip][j], av[ip], bv[j]);
        }
    }
}

// ---------------------------------------------------------------------------
// Full GEMM mainloop (double-buffered smem + register prefetch), 512 threads
// ---------------------------------------------------------------------------
template<bool BNT>
__device__ __forceinline__ void gemm_main(const float* __restrict__ A,
                                          const float* __restrict__ Bm,
                                          int lda, int ldb, int K,
                                          int r0, int c0,
                                          u64 acc[4][8], float* sm)
{
    float* As0 = sm;
    float* As1 = sm + BK*ASTR;
    float* Bs0 = sm + 2*BK*ASTR;
    float* Bs1 = Bs0 + BK*BSTR;
    const int ty = threadIdx.x >> 4, tx = threadIdx.x & 15;

    float4 pa[2], pb;
    loadA(pa, A, lda, r0, 0);
    if (BNT) loadBt(pb, Bm, ldb, c0, 0); else loadBn(pb, Bm, ldb, c0, 0);
    storeA(As0, pa);
    if (BNT) storeBt(Bs0, pb); else storeBn(Bs0, pb);
    __syncthreads();

    const int nit = K / BK;
    for (int it = 0; it < nit; it++) {
        float* Ac = (it & 1) ? As1 : As0;
        float* Bc = (it & 1) ? Bs1 : Bs0;
        float* An = (it & 1) ? As0 : As1;
        float* Bn = (it & 1) ? Bs0 : Bs1;
        if (it + 1 < nit) {
            loadA(pa, A, lda, r0, (it+1)*BK);
            if (BNT) loadBt(pb, Bm, ldb, c0, (it+1)*BK);
            else     loadBn(pb, Bm, ldb, c0, (it+1)*BK);
        }
        compute_tile(acc, Ac, Bc, ty, tx);
        if (it + 1 < nit) {
            storeA(An, pa);
            if (BNT) storeBt(Bn, pb); else storeBn(Bn, pb);
        }
        __syncthreads();
    }
}

// accessor: row i = ty*8 + 2*ip + half, col j = tx*8 + j
#define ACCF(accf, ip, j, half) (accf)[((ip)*8 + (j))*2 + (half)]

// ---------------------------------------------------------------------------
// Kernel 1: UNIFIED input projection (R13 structure, 512 threads)
// ---------------------------------------------------------------------------
__global__ void __launch_bounds__(NT, 1) k_proj(const float* __restrict__ query,
                                                const float* __restrict__ value,
                                                const float* __restrict__ ipw,
                                                const float* __restrict__ ipb,
                                                const float* __restrict__ qpos,
                                                const float* __restrict__ vpos)
{
    extern __shared__ float sm[];
    const int id = blockIdx.x;
    const bool isQ = (id >= KV_TILES);

    int r0, c0;
    const float *A, *Wm, *bias, *pos;
    if (isQ) {
        const int id2 = id - KV_TILES;
        c0 = (id2 & 7)*BN;
        r0 = (id2 >> 3)*BM;
        A = query; Wm = ipw; bias = ipb; pos = qpos;
    } else {
        c0 = (id & 15)*BN;
        r0 = (id >> 4)*BM;
        A = value; Wm = ipw + (size_t)E*E; bias = ipb + E; pos = vpos;
    }

    u64 acc[4][8] = {};
    gemm_main<true>(A, Wm, E, E, E, r0, c0, acc, sm);
    const float* accf = reinterpret_cast<const float*>(acc);

    const int ty = threadIdx.x >> 4, tx = threadIdx.x & 15;
    const int cb = c0 + tx*8;
    float bb[8];
    #pragma unroll
    for (int j = 0; j < 8; j++) bb[j] = bias[cb + j];

    if (isQ) {
        const int h = cb >> 7, hd0 = cb & 127;
        #pragma unroll
        for (int ip = 0; ip < 4; ip++) {
            #pragma unroll
            for (int half = 0; half < 2; half++) {
                int m = r0 + ty*8 + ip*2 + half;
                int t = m >> 3, b = m & 7;
                const float* qp = pos + (((size_t)b*Tq + t)*E + cb)*2;
                float* dq = g_q + (((size_t)(b*H + h))*Tq + t)*HD + hd0;
                #pragma unroll
                for (int jp = 0; jp < 4; jp++) {
                    float v0 = ACCF(accf, ip, 2*jp,   half) + bb[2*jp];
                    float v1 = ACCF(accf, ip, 2*jp+1, half) + bb[2*jp+1];
                    float c0r = qp[4*jp+0], s0r = qp[4*jp+1];
                    float c1r = qp[4*jp+2], s1r = qp[4*jp+3];
                    dq[2*jp]   = SCALE*(v0*c0r - v1*s0r);
                    dq[2*jp+1] = SCALE*(v1*c1r + v0*s1r);
                }
            }
        }
    } else if (c0 < E) {     // K half: bias + RoPE -> g_k
        const int h = cb >> 7, hd0 = cb & 127;
        #pragma unroll
        for (int ip = 0; ip < 4; ip++) {
            #pragma unroll
            for (int half = 0; half < 2; half++) {
                int m = r0 + ty*8 + ip*2 + half;
                int s = m >> 3, b = m & 7;
                const float* vp = pos + (((size_t)b*Sk + s)*E + cb)*2;
                float* dk = g_k + (((size_t)(b*H + h))*Sk + s)*HD + hd0;
                #pragma unroll
                for (int jp = 0; jp < 4; jp++) {
                    float v0 = ACCF(accf, ip, 2*jp,   half) + bb[2*jp];
                    float v1 = ACCF(accf, ip, 2*jp+1, half) + bb[2*jp+1];
                    float c0r = vp[4*jp+0], s0r = vp[4*jp+1];
                    float c1r = vp[4*jp+2], s1r = vp[4*jp+3];
                    dk[2*jp]   = v0*c0r - v1*s0r;
                    dk[2*jp+1] = v1*c1r + v0*s1r;
                }
            }
        }
    } else {                 // V half: bias -> g_v
        const int e = cb - E;
        const int h = e >> 7, hd0 = e & 127;
        #pragma unroll
        for (int ip = 0; ip < 4; ip++) {
            #pragma unroll
            for (int half = 0; half < 2; half++) {
                int m = r0 + ty*8 + ip*2 + half;
                int s = m >> 3, b = m & 7;
                float* dv = g_v + (((size_t)(b*H + h))*Sk + s)*HD + hd0;
                #pragma unroll
                for (int j = 0; j < 8; j++)
                    dv[j] = ACCF(accf, ip, j, half) + bb[j];
            }
        }
    }
}

// ---------------------------------------------------------------------------
// Kernel 3: scores = q . k^T per (b,h), with pad mask -> g_w
// ---------------------------------------------------------------------------
__global__ void __launch_bounds__(NT, 1) k_scores(const int* __restrict__ mask)
{
    extern __shared__ float sm[];
    const int bh = blockIdx.z;
    const int b  = bh >> 3;
    const float* A  = g_q + (size_t)bh*Tq*HD;
    const float* Bm = g_k + (size_t)bh*Sk*HD;
    int r0 = blockIdx.y*BM, c0 = blockIdx.x*BN;
    u64 acc[4][8] = {};
    gemm_main<true>(A, Bm, HD, HD, HD, r0, c0, acc, sm);
    const float* accf = reinterpret_cast<const float*>(acc);

    const int ty = threadIdx.x >> 4, tx = threadIdx.x & 15;
    const int cb = c0 + tx*8;
    bool mskd[8];
    #pragma unroll
    for (int j = 0; j < 8; j++) mskd[j] = (mask[b*Sk + cb + j] != 0);
    #pragma unroll
    for (int ip = 0; ip < 4; ip++) {
        #pragma unroll
        for (int half = 0; half < 2; half++) {
            int t = r0 + ty*8 + ip*2 + half;
            float* dw = g_w + ((size_t)bh*Tq + t)*Sk + cb;
            #pragma unroll
            for (int j = 0; j < 8; j++)
                dw[j] = mskd[j] ? -1e30f : ACCF(accf, ip, j, half);
        }
    }
}

// ---------------------------------------------------------------------------
// Kernel 4: softmax per row over S=2048, in place (R13 verbatim)
// ---------------------------------------------------------------------------
__global__ void __launch_bounds__(256) k_softmax()
{
    __shared__ float sh[8];
    __shared__ float shb;
    const int rid = blockIdx.x;
    const int tid = threadIdx.x;

    float4* r4 = reinterpret_cast<float4*>(g_w + (size_t)rid*Sk);
    float4 v0 = r4[tid];
    float4 v1 = r4[tid + 256];

    float mx = fmaxf(fmaxf(fmaxf(v0.x,v0.y), fmaxf(v0.z,v0.w)),
                     fmaxf(fmaxf(v1.x,v1.y), fmaxf(v1.z,v1.w)));
    #pragma unroll
    for (int o = 16; o; o >>= 1) mx = fmaxf(mx, __shfl_xor_sync(0xffffffffu, mx, o));
    if ((tid & 31) == 0) sh[tid >> 5] = mx;
    __syncthreads();
    if (tid == 0) {
        float m2 = sh[0];
        #pragma unroll
        for (int i = 1; i < 8; i++) m2 = fmaxf(m2, sh[i]);
        shb = m2;
    }
    __syncthreads();
    mx = shb;
    __syncthreads();

    float e[8];
    e[0]=expf(v0.x-mx); e[1]=expf(v0.y-mx); e[2]=expf(v0.z-mx); e[3]=expf(v0.w-mx);
    e[4]=expf(v1.x-mx); e[5]=expf(v1.y-mx); e[6]=expf(v1.z-mx); e[7]=expf(v1.w-mx);
    float smv = e[0]+e[1]+e[2]+e[3]+e[4]+e[5]+e[6]+e[7];
    #pragma unroll
    for (int o = 16; o; o >>= 1) smv += __shfl_xor_sync(0xffffffffu, smv, o);
    if ((tid & 31) == 0) sh[tid >> 5] = smv;
    __syncthreads();
    if (tid == 0) {
        float tot = 0.f;
        #pragma unroll
        for (int i = 0; i < 8; i++) tot += sh[i];
        shb = 1.f / tot;
    }
    __syncthreads();
    const float inv = shb;

    r4[tid]       = make_float4(e[0]*inv, e[1]*inv, e[2]*inv, e[3]*inv);
    r4[tid + 256] = make_float4(e[4]*inv, e[5]*inv, e[6]*inv, e[7]*inv);
}

// ---------------------------------------------------------------------------
// Kernel 4b: wmean (R13 verbatim)
// ---------------------------------------------------------------------------
__global__ void __launch_bounds__(256) k_wmean(float* __restrict__ wmean)
{
    const size_t idx = (size_t)blockIdx.x*256 + threadIdx.x;
    const int s4 = (int)(idx & 511);
    const size_t bt = idx >> 9;
    const int b = (int)(bt >> 9), t = (int)(bt & 511);

    float4 a = make_float4(0.f, 0.f, 0.f, 0.f);
    #pragma unroll
    for (int h = 0; h < H; h++) {
        const float4 v = *reinterpret_cast<const float4*>(
            &g_w[(((size_t)(b*H + h))*Tq + t)*Sk + s4*4]);
        a.x += v.x; a.y += v.y; a.z += v.z; a.w += v.w;
    }
    a.x *= 0.125f; a.y *= 0.125f; a.z *= 0.125f; a.w *= 0.125f;
    *reinterpret_cast<float4*>(&wmean[bt*Sk + s4*4]) = a;
}

// ---------------------------------------------------------------------------
// Kernel 5: attn = weights @ v per (b,h) (NN GEMM, 512 threads)
// ---------------------------------------------------------------------------
__global__ void __launch_bounds__(NT, 1) k_attn()
{
    extern __shared__ float sm[];
    const int bh = blockIdx.z;
    const int b = bh >> 3, h = bh & 7;
    const float* A  = g_w + (size_t)bh*Tq*Sk;
    const float* Bm = g_v + (size_t)bh*Sk*HD;
    int r0 = blockIdx.y*BM;
    u64 acc[4][8] = {};
    gemm_main<false>(A, Bm, Sk, HD, Sk, r0, 0, acc, sm);
    const float* accf = reinterpret_cast<const float*>(acc);

    const int ty = threadIdx.x >> 4, tx = threadIdx.x & 15;
    const int cb = tx*8;
    #pragma unroll
    for (int ip = 0; ip < 4; ip++) {
        #pragma unroll
        for (int half = 0; half < 2; half++) {
            int t = r0 + ty*8 + ip*2 + half;
            float* da = g_attn + ((size_t)t*NB + b)*E + h*HD + cb;
            #pragma unroll
            for (int j = 0; j < 8; j++) da[j] = ACCF(accf, ip, j, half);
        }
    }
}

// ---------------------------------------------------------------------------
// Kernel 6: out-proj + bias + residual (512 threads)
// ---------------------------------------------------------------------------
__global__ void __launch_bounds__(NT, 1) k_outproj(const float* __restrict__ Wm,
                                                   const float* __restrict__ bias,
                                                   const float* __restrict__ query)
{
    extern __shared__ float sm[];
    int r0 = blockIdx.y*BM, c0 = blockIdx.x*BN;
    u64 acc[4][8] = {};
    gemm_main<true>(g_attn, Wm, E, E, E, r0, c0, acc, sm);
    const float* accf = reinterpret_cast<const float*>(acc);

    const int ty = threadIdx.x >> 4, tx = threadIdx.x & 15;
    const int cb = c0 + tx*8;
    float bb[8];
    #pragma unroll
    for (int j = 0; j < 8; j++) bb[j] = bias[cb + j];

    #pragma unroll
    for (int ip = 0; ip < 4; ip++) {
        #pragma unroll
        for (int half = 0; half < 2; half++) {
            int m = r0 + ty*8 + ip*2 + half;
            const float* qr = query + (size_t)m*E + cb;
            float* dp = g_pre + (size_t)m*E + cb;
            #pragma unroll
            for (int j = 0; j < 8; j++)
                dp[j] = ACCF(accf, ip, j, half) + bb[j] + qr[j];
        }
    }
}

// ---------------------------------------------------------------------------
// Kernel 7: LayerNorm per row (R13 verbatim)
// ---------------------------------------------------------------------------
__global__ void __launch_bounds__(256) k_ln(const float* __restrict__ lg,
                                            const float* __restrict__ lb,
                                            float* __restrict__ out)
{
    const int m = blockIdx.x, tid = threadIdx.x;
    __shared__ float sh[8];
    __shared__ float s_mu, s_rstd;

    float4 v = reinterpret_cast<const float4*>(g_pre + (size_t)m*E)[tid];
    float smv = v.x + v.y + v.z + v.w;
    #pragma unroll
    for (int o = 16; o; o >>= 1) smv += __shfl_xor_sync(0xffffffffu, smv, o);
    if ((tid & 31) == 0) sh[tid >> 5] = smv;
    __syncthreads();
    if (tid == 0) {
        float tot = 0.f;
        #pragma unroll
        for (int i = 0; i < 8; i++) tot += sh[i];
        s_mu = tot * (1.f/E);
    }
    __syncthreads();
    const float mu = s_mu;
    float dx0 = v.x-mu, dx1 = v.y-mu, dx2 = v.z-mu, dx3 = v.w-mu;
    float sq = dx0*dx0 + dx1*dx1 + dx2*dx2 + dx3*dx3;
    #pragma unroll
    for (int o = 16; o; o >>= 1) sq += __shfl_xor_sync(0xffffffffu, sq, o);
    if ((tid & 31) == 0) sh[tid >> 5] = sq;
    __syncthreads();
    if (tid == 0) {
        float tot = 0.f;
        #pragma unroll
        for (int i = 0; i < 8; i++) tot += sh[i];
        s_rstd = rsqrtf(tot * (1.f/E) + EPSF);
    }
    __syncthreads();
    const float rstd = s_rstd;

    float4 g4 = reinterpret_cast<const float4*>(lg)[tid];
    float4 b4 = reinterpret_cast<const float4*>(lb)[tid];
    float4 o4;
    o4.x = dx0*rstd*g4.x + b4.x;
    o4.y = dx1*rstd*g4.y + b4.y;
    o4.z = dx2*rstd*g4.z + b4.z;
    o4.w = dx3*rstd*g4.w + b4.w;
    reinterpret_cast<float4*>(out + (size_t)m*E)[tid] = o4;
}

// ---------------------------------------------------------------------------
extern "C" void kernel_launch(void* const* d_in, const int* in_sizes, int n_in,
                              void* d_out, int out_size)
{
    (void)in_sizes; (void)n_in; (void)out_size;
    const float* query = (const float*)d_in[0];
    const float* value = (const float*)d_in[1];
    const float* qpos  = (const float*)d_in[2];
    const float* vpos  = (const float*)d_in[3];
    const int*   mask  = (const int*)d_in[4];
    const float* ipw   = (const float*)d_in[5];
    const float* ipb   = (const float*)d_in[6];
    const float* ow    = (const float*)d_in[7];
    const float* ob    = (const float*)d_in[8];
    const float* lg    = (const float*)d_in[9];
    const float* lb    = (const float*)d_in[10];

    float* out   = (float*)d_out;                       // (T,B,E)
    float* wmean = out + (size_t)Tq*NB*E;               // (B,T,S)

    static bool attr_done = false;
    if (!attr_done) {
        cudaFuncSetAttribute(k_proj,    cudaFuncAttributeMaxDynamicSharedMemorySize, SMEMB);
        cudaFuncSetAttribute(k_scores,  cudaFuncAttributeMaxDynamicSharedMemorySize, SMEMB);
        cudaFuncSetAttribute(k_attn,    cudaFuncAttributeMaxDynamicSharedMemorySize, SMEMB);
        cudaFuncSetAttribute(k_outproj, cudaFuncAttributeMaxDynamicSharedMemorySize, SMEMB);
        attr_done = true;
    }

    k_proj   <<<KV_TILES + Q_TILES, NT, SMEMB>>>(query, value, ipw, ipb, qpos, vpos);
    k_scores <<<dim3(Sk/BN, Tq/BM, NB*H), NT, SMEMB>>>(mask);
    k_softmax<<<NB*H*Tq, 256>>>();
    k_wmean  <<<(NB*Tq*Sk/4)/256, 256>>>(wmean);
    k_attn   <<<dim3(1, Tq/BM, NB*H), NT, SMEMB>>>();
    k_outproj<<<dim3(E/BN, (Tq*NB)/BM), NT, SMEMB>>>(ow, ob, query);
    k_ln     <<<Tq*NB, 256>>>(lg, lb, out);
}

// round 17
// speedup vs baseline: 1.2007x; 1.2007x over previous
#include <cuda_runtime.h>
#include <math.h>
#include <stdint.h>
#include <stddef.h>

// Problem constants
#define Tq 512
#define Sk 2048
#define NB 8
#define E  1024
#define H  8
#define HD 128
#define EPSF 1e-5f
#define SCALE 0.08838834764831845f   // HD^-0.5

// GEMM tiling: 256x128 block tile, 16x8 micro-tile, 256 threads (R3 optimum)
#define BM 256
#define BN 128
#define BK 16
#define ASTR 260
#define BSTR 132
#define SMEMB ((2*BK*ASTR + 2*BK*BSTR) * 4)   // 50176 bytes

// Unified projection grid: KV tiles then Q tiles
#define KV_TILES 1024     // (2E/BN=16) x (Sk*NB/BM=64)
#define Q_TILES  128      // (E/BN=8)  x (Tq*NB/BM=16)

// Scratch (device globals: allocation-free per harness rules)
__device__ __align__(128) float g_q   [(size_t)NB*H*Tq*HD];
__device__ __align__(128) float g_k   [(size_t)NB*H*Sk*HD];
__device__ __align__(128) float g_v   [(size_t)NB*H*Sk*HD];
__device__ __align__(128) float g_w   [(size_t)NB*H*Tq*Sk];
__device__ __align__(128) float g_attn[(size_t)Tq*NB*E];
__device__ __align__(128) float g_pre [(size_t)Tq*NB*E];

typedef unsigned long long u64;

__device__ __forceinline__ u64 splat2(float x) {
    u64 r;
    asm("mov.b64 %0, {%1, %1};" : "=l"(r) : "f"(x));
    return r;
}
__device__ __forceinline__ void ffma2(u64 &d, u64 a, u64 b) {
    asm("fma.rn.f32x2 %0, %1, %2, %0;" : "+l"(d) : "l"(a), "l"(b));
}

// ---------------------------------------------------------------------------
// Loaders / stores (R3 verbatim)
// ---------------------------------------------------------------------------
__device__ __forceinline__ void loadA(float4 pa[4], const float* __restrict__ A,
                                      int lda, int r0, int k0) {
    const int tid = threadIdx.x;
    #pragma unroll
    for (int l = 0; l < 4; l++) {
        int idx = tid + l*256;
        int row = idx >> 2;
        int q   = (idx & 3) * 4;
        pa[l] = *reinterpret_cast<const float4*>(&A[(size_t)(r0+row)*lda + k0 + q]);
    }
}
__device__ __forceinline__ void storeA(float* As, const float4 pa[4]) {
    const int tid = threadIdx.x;
    #pragma unroll
    for (int l = 0; l < 4; l++) {
        int idx = tid + l*256;
        int row = idx >> 2;
        int q   = (idx & 3) * 4;
        As[(q+0)*ASTR + row] = pa[l].x;
        As[(q+1)*ASTR + row] = pa[l].y;
        As[(q+2)*ASTR + row] = pa[l].z;
        As[(q+3)*ASTR + row] = pa[l].w;
    }
}
__device__ __forceinline__ void loadBt(float4 pb[2], const float* __restrict__ Bm,
                                       int ldb, int c0, int k0) {
    const int tid = threadIdx.x;
    #pragma unroll
    for (int l = 0; l < 2; l++) {
        int idx = tid + l*256;
        int row = idx >> 2;
        int q   = (idx & 3) * 4;
        pb[l] = *reinterpret_cast<const float4*>(&Bm[(size_t)(c0+row)*ldb + k0 + q]);
    }
}
__device__ __forceinline__ void storeBt(float* Bs, const float4 pb[2]) {
    const int tid = threadIdx.x;
    #pragma unroll
    for (int l = 0; l < 2; l++) {
        int idx = tid + l*256;
        int row = idx >> 2;
        int q   = (idx & 3) * 4;
        Bs[(q+0)*BSTR + row] = pb[l].x;
        Bs[(q+1)*BSTR + row] = pb[l].y;
        Bs[(q+2)*BSTR + row] = pb[l].z;
        Bs[(q+3)*BSTR + row] = pb[l].w;
    }
}
__device__ __forceinline__ void loadBn(float4 pb[2], const float* __restrict__ Bm,
                                       int ldb, int c0, int k0) {
    const int tid = threadIdx.x;
    #pragma unroll
    for (int l = 0; l < 2; l++) {
        int idx = tid + l*256;
        int kk = idx >> 5;
        int c4 = (idx & 31) * 4;
        pb[l] = *reinterpret_cast<const float4*>(&Bm[(size_t)(k0+kk)*ldb + c0 + c4]);
    }
}
__device__ __forceinline__ void storeBn(float* Bs, const float4 pb[2]) {
    const int tid = threadIdx.x;
    #pragma unroll
    for (int l = 0; l < 2; l++) {
        int idx = tid + l*256;
        int kk = idx >> 5;
        int c4 = (idx & 31) * 4;
        *reinterpret_cast<float4*>(&Bs[kk*BSTR + c4]) = pb[l];
    }
}

// ---------------------------------------------------------------------------
// FFMA2 inner product over one BK tile (R3 verbatim)
// ---------------------------------------------------------------------------
__device__ __forceinline__ void compute_tile(u64 acc[8][8],
                                             const float* As, const float* Bs,
                                             int ty, int tx) {
    #pragma unroll
    for (int kk = 0; kk < BK; kk++) {
        const float* ap = As + kk*ASTR + ty*16;
        ulonglong2 a0 = *reinterpret_cast<const ulonglong2*>(ap);
        ulonglong2 a1 = *reinterpret_cast<const ulonglong2*>(ap + 4);
        ulonglong2 a2 = *reinterpret_cast<const ulonglong2*>(ap + 8);
        ulonglong2 a3 = *reinterpret_cast<const ulonglong2*>(ap + 12);
        u64 av[8] = {a0.x, a0.y, a1.x, a1.y, a2.x, a2.y, a3.x, a3.y};
        const float* bp = Bs + kk*BSTR + tx*8;
        float4 b0 = *reinterpret_cast<const float4*>(bp);
        float4 b1 = *reinterpret_cast<const float4*>(bp + 4);
        u64 bv[8];
        bv[0]=splat2(b0.x); bv[1]=splat2(b0.y); bv[2]=splat2(b0.z); bv[3]=splat2(b0.w);
        bv[4]=splat2(b1.x); bv[5]=splat2(b1.y); bv[6]=splat2(b1.z); bv[7]=splat2(b1.w);
        #pragma unroll
        for (int ip = 0; ip < 8; ip++) {
            #pragma unroll
            for (int j = 0; j < 8; j++)
                ffma2(acc[ip][j], av[ip], bv[j]);
        }
    }
}

// ---------------------------------------------------------------------------
// Full GEMM mainloop (R3 verbatim)
// ---------------------------------------------------------------------------
template<bool BNT>
__device__ __forceinline__ void gemm_main(const float* __restrict__ A,
                                          const float* __restrict__ Bm,
                                          int lda, int ldb, int K,
                                          int r0, int c0,
                                          u64 acc[8][8], float* sm)
{
    float* As0 = sm;
    float* As1 = sm + BK*ASTR;
    float* Bs0 = sm + 2*BK*ASTR;
    float* Bs1 = Bs0 + BK*BSTR;
    const int ty = threadIdx.x >> 4, tx = threadIdx.x & 15;

    float4 pa[4], pb[2];
    loadA(pa, A, lda, r0, 0);
    if (BNT) loadBt(pb, Bm, ldb, c0, 0); else loadBn(pb, Bm, ldb, c0, 0);
    storeA(As0, pa);
    if (BNT) storeBt(Bs0, pb); else storeBn(Bs0, pb);
    __syncthreads();

    const int nit = K / BK;
    for (int it = 0; it < nit; it++) {
        float* Ac = (it & 1) ? As1 : As0;
        float* Bc = (it & 1) ? Bs1 : Bs0;
        float* An = (it & 1) ? As0 : As1;
        float* Bn = (it & 1) ? Bs0 : Bs1;
        if (it + 1 < nit) {
            loadA(pa, A, lda, r0, (it+1)*BK);
            if (BNT) loadBt(pb, Bm, ldb, c0, (it+1)*BK);
            else     loadBn(pb, Bm, ldb, c0, (it+1)*BK);
        }
        compute_tile(acc, Ac, Bc, ty, tx);
        if (it + 1 < nit) {
            storeA(An, pa);
            if (BNT) storeBt(Bn, pb); else storeBn(Bn, pb);
        }
        __syncthreads();
    }
}

// accessor: row i = ty*16 + 2*ip + half, col j
#define ACCF(accf, ip, j, half) (accf)[((ip)*8 + (j))*2 + (half)]

// ---------------------------------------------------------------------------
// Kernel 1: UNIFIED input projection (R13, committed).
// ---------------------------------------------------------------------------
__global__ void __launch_bounds__(256, 1) k_proj(const float* __restrict__ query,
                                                 const float* __restrict__ value,
                                                 const float* __restrict__ ipw,
                                                 const float* __restrict__ ipb,
                                                 const float* __restrict__ qpos,
                                                 const float* __restrict__ vpos)
{
    extern __shared__ float sm[];
    const int id = blockIdx.x;
    const bool isQ = (id >= KV_TILES);

    int r0, c0;
    const float *A, *Wm, *bias, *pos;
    if (isQ) {
        const int id2 = id - KV_TILES;      // 128 tiles: 8 cols x 16 rows
        c0 = (id2 & 7)*BN;
        r0 = (id2 >> 3)*BM;
        A = query; Wm = ipw; bias = ipb; pos = qpos;
    } else {                                // 1024 tiles: 16 cols x 64 rows
        c0 = (id & 15)*BN;
        r0 = (id >> 4)*BM;
        A = value; Wm = ipw + (size_t)E*E; bias = ipb + E; pos = vpos;
    }

    u64 acc[8][8] = {};
    gemm_main<true>(A, Wm, E, E, E, r0, c0, acc, sm);
    const float* accf = reinterpret_cast<const float*>(acc);

    const int ty = threadIdx.x >> 4, tx = threadIdx.x & 15;
    const int cb = c0 + tx*8;
    float bb[8];
    #pragma unroll
    for (int j = 0; j < 8; j++) bb[j] = bias[cb + j];

    if (isQ) {
        const int h = cb >> 7, hd0 = cb & 127;
        #pragma unroll
        for (int ip = 0; ip < 8; ip++) {
            #pragma unroll
            for (int half = 0; half < 2; half++) {
                int m = r0 + ty*16 + ip*2 + half;
                int t = m >> 3, b = m & 7;
                const float* qp = pos + (((size_t)b*Tq + t)*E + cb)*2;
                float* dq = g_q + (((size_t)(b*H + h))*Tq + t)*HD + hd0;
                #pragma unroll
                for (int jp = 0; jp < 4; jp++) {
                    float v0 = ACCF(accf, ip, 2*jp,   half) + bb[2*jp];
                    float v1 = ACCF(accf, ip, 2*jp+1, half) + bb[2*jp+1];
                    float c0r = qp[4*jp+0], s0r = qp[4*jp+1];
                    float c1r = qp[4*jp+2], s1r = qp[4*jp+3];
                    dq[2*jp]   = SCALE*(v0*c0r - v1*s0r);
                    dq[2*jp+1] = SCALE*(v1*c1r + v0*s1r);
                }
            }
        }
    } else if (c0 < E) {     // K half: bias + RoPE -> g_k
        const int h = cb >> 7, hd0 = cb & 127;
        #pragma unroll
        for (int ip = 0; ip < 8; ip++) {
            #pragma unroll
            for (int half = 0; half < 2; half++) {
                int m = r0 + ty*16 + ip*2 + half;
                int s = m >> 3, b = m & 7;
                const float* vp = pos + (((size_t)b*Sk + s)*E + cb)*2;
                float* dk = g_k + (((size_t)(b*H + h))*Sk + s)*HD + hd0;
                #pragma unroll
                for (int jp = 0; jp < 4; jp++) {
                    float v0 = ACCF(accf, ip, 2*jp,   half) + bb[2*jp];
                    float v1 = ACCF(accf, ip, 2*jp+1, half) + bb[2*jp+1];
                    float c0r = vp[4*jp+0], s0r = vp[4*jp+1];
                    float c1r = vp[4*jp+2], s1r = vp[4*jp+3];
                    dk[2*jp]   = v0*c0r - v1*s0r;
                    dk[2*jp+1] = v1*c1r + v0*s1r;
                }
            }
        }
    } else {                 // V half: bias -> g_v
        const int e = cb - E;
        const int h = e >> 7, hd0 = e & 127;
        #pragma unroll
        for (int ip = 0; ip < 8; ip++) {
            #pragma unroll
            for (int half = 0; half < 2; half++) {
                int m = r0 + ty*16 + ip*2 + half;
                int s = m >> 3, b = m & 7;
                float* dv = g_v + (((size_t)(b*H + h))*Sk + s)*HD + hd0;
                #pragma unroll
                for (int j = 0; j < 8; j++)
                    dv[j] = ACCF(accf, ip, j, half) + bb[j];
            }
        }
    }
}

// ---------------------------------------------------------------------------
// Kernel 3: scores = q . k^T per (b,h), with pad mask -> g_w
// ---------------------------------------------------------------------------
__global__ void __launch_bounds__(256, 1) k_scores(const int* __restrict__ mask)
{
    extern __shared__ float sm[];
    const int bh = blockIdx.z;
    const int b  = bh >> 3;
    const float* A  = g_q + (size_t)bh*Tq*HD;
    const float* Bm = g_k + (size_t)bh*Sk*HD;
    int r0 = blockIdx.y*BM, c0 = blockIdx.x*BN;
    u64 acc[8][8] = {};
    gemm_main<true>(A, Bm, HD, HD, HD, r0, c0, acc, sm);
    const float* accf = reinterpret_cast<const float*>(acc);

    const int ty = threadIdx.x >> 4, tx = threadIdx.x & 15;
    const int cb = c0 + tx*8;
    bool mskd[8];
    #pragma unroll
    for (int j = 0; j < 8; j++) mskd[j] = (mask[b*Sk + cb + j] != 0);
    #pragma unroll
    for (int ip = 0; ip < 8; ip++) {
        #pragma unroll
        for (int half = 0; half < 2; half++) {
            int t = r0 + ty*16 + ip*2 + half;
            float* dw = g_w + ((size_t)bh*Tq + t)*Sk + cb;
            #pragma unroll
            for (int j = 0; j < 8; j++)
                dw[j] = mskd[j] ? -1e30f : ACCF(accf, ip, j, half);
        }
    }
}

// ---------------------------------------------------------------------------
// Kernel 4: softmax per row over S=2048, normalizes weights in place (R13).
// ---------------------------------------------------------------------------
__global__ void __launch_bounds__(256) k_softmax()
{
    __shared__ float sh[8];
    __shared__ float shb;
    const int rid = blockIdx.x;
    const int tid = threadIdx.x;

    float4* r4 = reinterpret_cast<float4*>(g_w + (size_t)rid*Sk);
    float4 v0 = r4[tid];
    float4 v1 = r4[tid + 256];

    float mx = fmaxf(fmaxf(fmaxf(v0.x,v0.y), fmaxf(v0.z,v0.w)),
                     fmaxf(fmaxf(v1.x,v1.y), fmaxf(v1.z,v1.w)));
    #pragma unroll
    for (int o = 16; o; o >>= 1) mx = fmaxf(mx, __shfl_xor_sync(0xffffffffu, mx, o));
    if ((tid & 31) == 0) sh[tid >> 5] = mx;
    __syncthreads();
    if (tid == 0) {
        float m2 = sh[0];
        #pragma unroll
        for (int i = 1; i < 8; i++) m2 = fmaxf(m2, sh[i]);
        shb = m2;
    }
    __syncthreads();
    mx = shb;
    __syncthreads();

    float e[8];
    e[0]=expf(v0.x-mx); e[1]=expf(v0.y-mx); e[2]=expf(v0.z-mx); e[3]=expf(v0.w-mx);
    e[4]=expf(v1.x-mx); e[5]=expf(v1.y-mx); e[6]=expf(v1.z-mx); e[7]=expf(v1.w-mx);
    float smv = e[0]+e[1]+e[2]+e[3]+e[4]+e[5]+e[6]+e[7];
    #pragma unroll
    for (int o = 16; o; o >>= 1) smv += __shfl_xor_sync(0xffffffffu, smv, o);
    if ((tid & 31) == 0) sh[tid >> 5] = smv;
    __syncthreads();
    if (tid == 0) {
        float tot = 0.f;
        #pragma unroll
        for (int i = 0; i < 8; i++) tot += sh[i];
        shb = 1.f / tot;
    }
    __syncthreads();
    const float inv = shb;

    r4[tid]       = make_float4(e[0]*inv, e[1]*inv, e[2]*inv, e[3]*inv);
    r4[tid + 256] = make_float4(e[4]*inv, e[5]*inv, e[6]*inv, e[7]*inv);
}

// ---------------------------------------------------------------------------
// Kernel 4b: wmean[b,t,s] = mean over h of g_w[b,h,t,s] (R13)
// ---------------------------------------------------------------------------
__global__ void __launch_bounds__(256) k_wmean(float* __restrict__ wmean)
{
    const size_t idx = (size_t)blockIdx.x*256 + threadIdx.x; // float4 index
    const int s4 = (int)(idx & 511);
    const size_t bt = idx >> 9;
    const int b = (int)(bt >> 9), t = (int)(bt & 511);

    float4 a = make_float4(0.f, 0.f, 0.f, 0.f);
    #pragma unroll
    for (int h = 0; h < H; h++) {
        const float4 v = *reinterpret_cast<const float4*>(
            &g_w[(((size_t)(b*H + h))*Tq + t)*Sk + s4*4]);
        a.x += v.x; a.y += v.y; a.z += v.z; a.w += v.w;
    }
    a.x *= 0.125f; a.y *= 0.125f; a.z *= 0.125f; a.w *= 0.125f;
    *reinterpret_cast<float4*>(&wmean[bt*Sk + s4*4]) = a;
}

// ---------------------------------------------------------------------------
// Kernel 5: attn = weights @ v per (b,h) (NN GEMM) (R13)
// ---------------------------------------------------------------------------
__global__ void __launch_bounds__(256, 1) k_attn()
{
    extern __shared__ float sm[];
    const int bh = blockIdx.z;
    const int b = bh >> 3, h = bh & 7;
    const float* A  = g_w + (size_t)bh*Tq*Sk;
    const float* Bm = g_v + (size_t)bh*Sk*HD;
    int r0 = blockIdx.y*BM;
    u64 acc[8][8] = {};
    gemm_main<false>(A, Bm, Sk, HD, Sk, r0, 0, acc, sm);
    const float* accf = reinterpret_cast<const float*>(acc);

    const int ty = threadIdx.x >> 4, tx = threadIdx.x & 15;
    const int cb = tx*8;
    #pragma unroll
    for (int ip = 0; ip < 8; ip++) {
        #pragma unroll
        for (int half = 0; half < 2; half++) {
            int t = r0 + ty*16 + ip*2 + half;
            float* da = g_attn + ((size_t)t*NB + b)*E + h*HD + cb;
            #pragma unroll
            for (int j = 0; j < 8; j++) da[j] = ACCF(accf, ip, j, half);
        }
    }
}

// ---------------------------------------------------------------------------
// Kernel 6: out-proj + bias + residual (R13)
// ---------------------------------------------------------------------------
__global__ void __launch_bounds__(256, 1) k_outproj(const float* __restrict__ Wm,
                                                    const float* __restrict__ bias,
                                                    const float* __restrict__ query)
{
    extern __shared__ float sm[];
    int r0 = blockIdx.y*BM, c0 = blockIdx.x*BN;
    u64 acc[8][8] = {};
    gemm_main<true>(g_attn, Wm, E, E, E, r0, c0, acc, sm);
    const float* accf = reinterpret_cast<const float*>(acc);

    const int ty = threadIdx.x >> 4, tx = threadIdx.x & 15;
    const int cb = c0 + tx*8;
    float bb[8];
    #pragma unroll
    for (int j = 0; j < 8; j++) bb[j] = bias[cb + j];

    #pragma unroll
    for (int ip = 0; ip < 8; ip++) {
        #pragma unroll
        for (int half = 0; half < 2; half++) {
            int m = r0 + ty*16 + ip*2 + half;
            const float* qr = query + (size_t)m*E + cb;
            float* dp = g_pre + (size_t)m*E + cb;
            #pragma unroll
            for (int j = 0; j < 8; j++)
                dp[j] = ACCF(accf, ip, j, half) + bb[j] + qr[j];
        }
    }
}

// ---------------------------------------------------------------------------
// Kernel 7: LayerNorm per row (R13)
// ---------------------------------------------------------------------------
__global__ void __launch_bounds__(256) k_ln(const float* __restrict__ lg,
                                            const float* __restrict__ lb,
                                            float* __restrict__ out)
{
    const int m = blockIdx.x, tid = threadIdx.x;
    __shared__ float sh[8];
    __shared__ float s_mu, s_rstd;

    float4 v = reinterpret_cast<const float4*>(g_pre + (size_t)m*E)[tid];
    float smv = v.x + v.y + v.z + v.w;
    #pragma unroll
    for (int o = 16; o; o >>= 1) smv += __shfl_xor_sync(0xffffffffu, smv, o);
    if ((tid & 31) == 0) sh[tid >> 5] = smv;
    __syncthreads();
    if (tid == 0) {
        float tot = 0.f;
        #pragma unroll
        for (int i = 0; i < 8; i++) tot += sh[i];
        s_mu = tot * (1.f/E);
    }
    __syncthreads();
    const float mu = s_mu;
    float dx0 = v.x-mu, dx1 = v.y-mu, dx2 = v.z-mu, dx3 = v.w-mu;
    float sq = dx0*dx0 + dx1*dx1 + dx2*dx2 + dx3*dx3;
    #pragma unroll
    for (int o = 16; o; o >>= 1) sq += __shfl_xor_sync(0xffffffffu, sq, o);
    if ((tid & 31) == 0) sh[tid >> 5] = sq;
    __syncthreads();
    if (tid == 0) {
        float tot = 0.f;
        #pragma unroll
        for (int i = 0; i < 8; i++) tot += sh[i];
        s_rstd = rsqrtf(tot * (1.f/E) + EPSF);
    }
    __syncthreads();
    const float rstd = s_rstd;

    float4 g4 = reinterpret_cast<const float4*>(lg)[tid];
    float4 b4 = reinterpret_cast<const float4*>(lb)[tid];
    float4 o4;
    o4.x = dx0*rstd*g4.x + b4.x;
    o4.y = dx1*rstd*g4.y + b4.y;
    o4.z = dx2*rstd*g4.z + b4.z;
    o4.w = dx3*rstd*g4.w + b4.w;
    reinterpret_cast<float4*>(out + (size_t)m*E)[tid] = o4;
}

// ---------------------------------------------------------------------------
extern "C" void kernel_launch(void* const* d_in, const int* in_sizes, int n_in,
                              void* d_out, int out_size)
{
    (void)in_sizes; (void)n_in; (void)out_size;
    const float* query = (const float*)d_in[0];
    const float* value = (const float*)d_in[1];
    const float* qpos  = (const float*)d_in[2];
    const float* vpos  = (const float*)d_in[3];
    const int*   mask  = (const int*)d_in[4];
    const float* ipw   = (const float*)d_in[5];
    const float* ipb   = (const float*)d_in[6];
    const float* ow    = (const float*)d_in[7];
    const float* ob    = (const float*)d_in[8];
    const float* lg    = (const float*)d_in[9];
    const float* lb    = (const float*)d_in[10];

    float* out   = (float*)d_out;                       // (T,B,E)
    float* wmean = out + (size_t)Tq*NB*E;               // (B,T,S)

    static bool init_done = false;
    static cudaStream_t s2;
    static cudaEvent_t ev_fork, ev_join;
    if (!init_done) {
        cudaFuncSetAttribute(k_proj,    cudaFuncAttributeMaxDynamicSharedMemorySize, SMEMB);
        cudaFuncSetAttribute(k_scores,  cudaFuncAttributeMaxDynamicSharedMemorySize, SMEMB);
        cudaFuncSetAttribute(k_attn,    cudaFuncAttributeMaxDynamicSharedMemorySize, SMEMB);
        cudaFuncSetAttribute(k_outproj, cudaFuncAttributeMaxDynamicSharedMemorySize, SMEMB);
        cudaStreamCreateWithFlags(&s2, cudaStreamNonBlocking);
        cudaEventCreateWithFlags(&ev_fork, cudaEventDisableTiming);
        cudaEventCreateWithFlags(&ev_join, cudaEventDisableTiming);
        init_done = true;
    }

    // main chain on the capture (default) stream
    k_proj   <<<KV_TILES + Q_TILES, 256, SMEMB>>>(query, value, ipw, ipb, qpos, vpos);
    k_scores <<<dim3(Sk/BN, Tq/BM, NB*H), 256, SMEMB>>>(mask);
    k_softmax<<<NB*H*Tq, 256>>>();

    // fork: wmean runs concurrently with attn/outproj/ln (nothing reads wmean)
    cudaEventRecord(ev_fork, 0);
    cudaStreamWaitEvent(s2, ev_fork, 0);
    k_wmean  <<<(NB*Tq*Sk/4)/256, 256, 0, s2>>>(wmean);
    cudaEventRecord(ev_join, s2);

    k_attn   <<<dim3(1, Tq/BM, NB*H), 256, SMEMB>>>();
    k_outproj<<<dim3(E/BN, (Tq*NB)/BM), 256, SMEMB>>>(ow, ob, query);
    k_ln     <<<Tq*NB, 256>>>(lg, lb, out);

    // join before graph end
    cudaStreamWaitEvent(0, ev_join, 0);
}